// round 13
// baseline (speedup 1.0000x reference)
#include <cuda_runtime.h>
#include <math.h>

#define Bsz 8192
#define Dd  1024
#define Rr  64
#define TB  8
#define NT  256

typedef unsigned long long ull;

// ---- Yoshida 4th-order coefficients ----
constexpr double kCbrt2 = 1.2599210498948731647672106072782;
constexpr double kW1 = 1.0 / (2.0 - kCbrt2);
constexpr double kW0 = -kCbrt2 * kW1;
constexpr double kDT = 0.01;

#define C1DT  ((float)((kW1 * 0.5) * kDT))
#define C2DT  ((float)(((kW0 + kW1) * 0.5) * kDT))
#define C4DT  C1DT
#define C41DT ((float)(kW1 * kDT))          // (C4 + C1) * dt
#define D1DT  ((float)(kW1 * kDT))
#define D2DT  ((float)(kW0 * kDT))

#define PLASTICITY    0.1f
#define SING_THRESH   10.0f
#define SING_STRENGTH 20.0f

// ---- packed f32x2 helpers (Blackwell) ----
__device__ __forceinline__ ull splat2(float x) {
    ull r; asm("mov.b64 %0, {%1, %1};" : "=l"(r) : "f"(x)); return r;
}
__device__ __forceinline__ ull fma2(ull a, ull b, ull c) {
    ull d; asm("fma.rn.f32x2 %0, %1, %2, %3;" : "=l"(d) : "l"(a), "l"(b), "l"(c)); return d;
}
__device__ __forceinline__ ull add2(ull a, ull b) {
    ull d; asm("add.rn.f32x2 %0, %1, %2;" : "=l"(d) : "l"(a), "l"(b)); return d;
}
__device__ __forceinline__ float2 unpk2(ull v) {
    float2 r; asm("mov.b64 {%0, %1}, %2;" : "=f"(r.x), "=f"(r.y) : "l"(v)); return r;
}
__device__ __forceinline__ float tanh_fast(float x) {
    float r; asm("tanh.approx.f32 %0, %1;" : "=f"(r) : "f"(x)); return r;
}

// Fused PQ block: 4 d's, 8 rows, one r-pair per matrix.
// A[0..7] = P rows (v.U), A[8..15] = Q rows (v.Vw). Shared splats.
__device__ __forceinline__ void pq_block(const float* __restrict__ sb, int d,
                                         const ull* u, const ull* w, ull* A)
{
    #pragma unroll
    for (int half = 0; half < 2; ++half) {
        float4 sv[4];
        #pragma unroll
        for (int j = 0; j < 4; ++j)
            sv[j] = *(const float4*)(sb + (half * 4 + j) * Dd + d);
        #pragma unroll
        for (int dd = 0; dd < 4; ++dd) {
            #pragma unroll
            for (int j = 0; j < 4; ++j) {
                const float f = (dd == 0) ? sv[j].x : (dd == 1) ? sv[j].y
                              : (dd == 2) ? sv[j].z : sv[j].w;
                const ull sp = splat2(f);
                const int row = half * 4 + j;
                A[row]     = fma2(sp, u[dd], A[row]);
                A[8 + row] = fma2(sp, w[dd], A[8 + row]);
            }
        }
    }
}

#define PQ_LOAD(ub, wb, dbase)                                              \
    do {                                                                    \
        _Pragma("unroll")                                                   \
        for (int dd = 0; dd < 4; ++dd) {                                    \
            ub[dd] = *(const ull*)(mu + (size_t)((dbase) + dd) * Rr);       \
            wb[dd] = *(const ull*)(mv + (size_t)((dbase) + dd) * Rr);       \
        }                                                                   \
    } while (0)

// Fused pass: P = v.U and Q = v.Vw over a 128-d slice, 8 rows, r-pair r2.
// Two-buffer rotation: no register copies, prefetch distance = 2 blocks.
__device__ __forceinline__ void pq_pass(const float* __restrict__ st,
                                        const float* __restrict__ U,
                                        const float* __restrict__ Vw,
                                        int r2, int d0, ull* A)
{
    #pragma unroll
    for (int c = 0; c < 16; ++c) A[c] = 0ull;
    const float* sb = st + d0;
    const float* mu = U  + (size_t)d0 * Rr + r2;
    const float* mv = Vw + (size_t)d0 * Rr + r2;

    ull u0[4], w0[4], u1[4], w1[4];
    PQ_LOAD(u0, w0, 0);
    PQ_LOAD(u1, w1, 4);

    #pragma unroll 1
    for (int d = 0; d < 112; d += 8) {
        pq_block(sb, d, u0, w0, A);
        PQ_LOAD(u0, w0, d + 8);
        pq_block(sb, d + 4, u1, w1, A);
        PQ_LOAD(u1, w1, d + 12);
    }
    pq_block(sb, 112, u0, w0, A);
    PQ_LOAD(u0, w0, 120);
    pq_block(sb, 116, u1, w1, A);
    PQ_LOAD(u1, w1, 124);
    pq_block(sb, 120, u0, w0, A);
    pq_block(sb, 124, u1, w1, A);
}

// Init pass: B[0..7] = x.Vw rows over a 128-d slice.
__device__ __forceinline__ void m_init_pass(const float* __restrict__ st,
                                            const float* __restrict__ Vw,
                                            int r2, int d0, ull* B)
{
    #pragma unroll
    for (int c = 0; c < 8; ++c) B[c] = 0ull;
    const float* sb = st + d0;
    const float* mv = Vw + (size_t)d0 * Rr + r2;
    #pragma unroll 1
    for (int d = 0; d < 128; d += 4) {
        ull w[4];
        #pragma unroll
        for (int dd = 0; dd < 4; ++dd)
            w[dd] = *(const ull*)(mv + (size_t)(d + dd) * Rr);
        #pragma unroll
        for (int half = 0; half < 2; ++half) {
            float4 sv[4];
            #pragma unroll
            for (int j = 0; j < 4; ++j)
                sv[j] = *(const float4*)(sb + (half * 4 + j) * Dd + d);
            #pragma unroll
            for (int dd = 0; dd < 4; ++dd) {
                #pragma unroll
                for (int j = 0; j < 4; ++j) {
                    const float f = (dd == 0) ? sv[j].x : (dd == 1) ? sv[j].y
                                  : (dd == 2) ? sv[j].z : sv[j].w;
                    B[half * 4 + j] = fma2(splat2(f), w[dd], B[half * 4 + j]);
                }
            }
        }
    }
}

// Balanced-tree reduce of 8 SMEM partials (stride 32 ull) at base+rg.
__device__ __forceinline__ ull tree8(const ull* __restrict__ base, int rg)
{
    ull t[8];
    #pragma unroll
    for (int p = 0; p < 8; ++p)
        t[p] = base[p * 32 + rg];
    #pragma unroll
    for (int p = 0; p < 4; ++p) t[p] = add2(t[p], t[p + 4]);
    t[0] = add2(t[0], t[2]);
    t[1] = add2(t[1], t[3]);
    return add2(t[0], t[1]);
}

// Phase-3 2-row block: Acc[k*4 + rowpair] += q(rows, r..r+1) * W splats.
__device__ __forceinline__ void gw2(const float* __restrict__ qs, int r,
                                    const float4 wA, const float4 wB, ull* Acc)
{
    const ulonglong2 qa0 = *(const ulonglong2*)(qs + r * TB);
    const ulonglong2 qb0 = *(const ulonglong2*)(qs + r * TB + 4);
    const ulonglong2 qa1 = *(const ulonglong2*)(qs + (r + 1) * TB);
    const ulonglong2 qb1 = *(const ulonglong2*)(qs + (r + 1) * TB + 4);
    {
        const ull s0 = splat2(wA.x), s1 = splat2(wA.y);
        const ull s2 = splat2(wA.z), s3 = splat2(wA.w);
        Acc[0]  = fma2(qa0.x, s0, Acc[0]);  Acc[1]  = fma2(qa0.y, s0, Acc[1]);
        Acc[2]  = fma2(qb0.x, s0, Acc[2]);  Acc[3]  = fma2(qb0.y, s0, Acc[3]);
        Acc[4]  = fma2(qa0.x, s1, Acc[4]);  Acc[5]  = fma2(qa0.y, s1, Acc[5]);
        Acc[6]  = fma2(qb0.x, s1, Acc[6]);  Acc[7]  = fma2(qb0.y, s1, Acc[7]);
        Acc[8]  = fma2(qa0.x, s2, Acc[8]);  Acc[9]  = fma2(qa0.y, s2, Acc[9]);
        Acc[10] = fma2(qb0.x, s2, Acc[10]); Acc[11] = fma2(qb0.y, s2, Acc[11]);
        Acc[12] = fma2(qa0.x, s3, Acc[12]); Acc[13] = fma2(qa0.y, s3, Acc[13]);
        Acc[14] = fma2(qb0.x, s3, Acc[14]); Acc[15] = fma2(qb0.y, s3, Acc[15]);
    }
    {
        const ull s0 = splat2(wB.x), s1 = splat2(wB.y);
        const ull s2 = splat2(wB.z), s3 = splat2(wB.w);
        Acc[0]  = fma2(qa1.x, s0, Acc[0]);  Acc[1]  = fma2(qa1.y, s0, Acc[1]);
        Acc[2]  = fma2(qb1.x, s0, Acc[2]);  Acc[3]  = fma2(qb1.y, s0, Acc[3]);
        Acc[4]  = fma2(qa1.x, s1, Acc[4]);  Acc[5]  = fma2(qa1.y, s1, Acc[5]);
        Acc[6]  = fma2(qb1.x, s1, Acc[6]);  Acc[7]  = fma2(qb1.y, s1, Acc[7]);
        Acc[8]  = fma2(qa1.x, s2, Acc[8]);  Acc[9]  = fma2(qa1.y, s2, Acc[9]);
        Acc[10] = fma2(qb1.x, s2, Acc[10]); Acc[11] = fma2(qb1.y, s2, Acc[11]);
        Acc[12] = fma2(qa1.x, s3, Acc[12]); Acc[13] = fma2(qa1.y, s3, Acc[13]);
        Acc[14] = fma2(qb1.x, s3, Acc[14]); Acc[15] = fma2(qb1.y, s3, Acc[15]);
    }
}

__global__ void __launch_bounds__(NT, 2)
yoshida_kernel(const float* __restrict__ x_in,
               const float* __restrict__ v_in,
               const float* __restrict__ force,
               const float* __restrict__ U,     // [D, R]
               const float* __restrict__ Wm,    // [R, D]
               const float* __restrict__ Vw,    // [D, R]
               const int*   __restrict__ steps_p,
               float* __restrict__ out)         // [x(B*D) ; v(B*D)]
{
    extern __shared__ float smem[];
    float* xs     = smem;                       // 8192 floats
    float* vs     = xs + TB * Dd;               // 8192
    float* qs     = vs + TB * Dd;               // 512  (qs[r*TB + row], sing folded)
    float* sing_s = qs + Rr * TB;               // 8
    ull*   part   = (ull*)(sing_s + TB);        // 16*256 ull = 32KB
    ull*   Mst    = part + 16 * 256;            // 256 ull = 2KB  (M state)

    const int tid  = threadIdx.x;
    const int row0 = blockIdx.x * TB;

    float4* sx4 = (float4*)xs;
    float4* sv4 = (float4*)vs;

    // ---- fused-pass mapping: 32 r-pairs x 8 d-slices ----
    const int rg = tid & 31;                    // r-pair 0..31
    const int r2 = rg * 2;
    const int ds = tid >> 5;                    // 0..7
    const int d0 = ds * 128;
    // ---- reduce mapping: 8 rows x 32 r-pairs ----
    const int rc = tid >> 5;                    // row 0..7
    // ---- phase-3 mapping: 256 k-quads, all 8 rows ----
    const int k4 = tid * 4;
    // ---- drift mapping: warp per row ----
    const int drow = tid >> 5;
    const int lane = tid & 31;

    // ---- load state tile ----
    {
        const float4* gx = (const float4*)(x_in + (size_t)row0 * Dd);
        const float4* gv = (const float4*)(v_in + (size_t)row0 * Dd);
        #pragma unroll
        for (int i = tid; i < TB * Dd / 4; i += NT) {
            sx4[i] = gx[i];
            sv4[i] = gv[i];
        }
    }
    __syncthreads();

    // ---- init M state: M = x0 . Vw ----
    {
        ull B[8];
        m_init_pass(xs, Vw, r2, d0, B);
        #pragma unroll
        for (int c = 0; c < 8; ++c)
            part[c * 256 + ds * 32 + rg] = B[c];
        __syncthreads();
        Mst[rc * 32 + rg] = tree8(part + rc * 256, rg);
    }

    const int nkicks = 3 * (*steps_p);

    for (int k = 0; k < nkicks; ++k) {
        const int sub = k - (k / 3) * 3;
        const float cdt = (k == 0) ? C1DT : (sub == 0) ? C41DT : C2DT;
        const float ddt = (sub == 1) ? D2DT : D1DT;

        __syncthreads();   // vs from prev kick visible; part readers done

        ull A[16];

        // ---- fused PQ-pass: P = v.U, Q = v.Vw (pre-kick v) ----
        pq_pass(vs, U, Vw, r2, d0, A);
        #pragma unroll
        for (int c = 0; c < 16; ++c)
            part[c * 256 + ds * 32 + rg] = A[c];

        // ---- drift + sing fused (warp per row, packed FMA2) ----
        {
            ulonglong2* xr = (ulonglong2*)(xs + drow * Dd);
            const ulonglong2* vr = (const ulonglong2*)(vs + drow * Dd);
            const ull cd2 = splat2(cdt);
            ull acc2 = 0ull;
            #pragma unroll
            for (int i = 0; i < 8; ++i) {
                ulonglong2 xv = xr[lane + 32 * i];
                const ulonglong2 vv = vr[lane + 32 * i];
                xv.x = fma2(cd2, vv.x, xv.x);
                xv.y = fma2(cd2, vv.y, xv.y);
                acc2 = fma2(xv.x, xv.x, acc2);
                acc2 = fma2(xv.y, xv.y, acc2);
                xr[lane + 32 * i] = xv;
            }
            const float2 a2 = unpk2(acc2);
            float acc = a2.x + a2.y;
            #pragma unroll
            for (int o = 16; o; o >>= 1)
                acc += __shfl_xor_sync(0xffffffffu, acc, o);
            if (lane == 0)
                sing_s[drow] = 1.0f + SING_STRENGTH * __expf(-acc * (1.0f / SING_THRESH));
        }
        __syncthreads();   // partials + sing ready

        // ---- force prefetch for phase 3 (hides L2 latency under reduce) ----
        float4 fpre[8];
        #pragma unroll
        for (int j = 0; j < 8; ++j)
            fpre[j] = *(const float4*)(force + (size_t)(row0 + j) * Dd + k4);

        // ---- combined reduce: P, Q -> M update -> q epilogue ----
        {
            const ull accP = tree8(part + rc * 256, rg);
            const ull accQ = tree8(part + (8 + rc) * 256, rg);
            ull m = Mst[rc * 32 + rg];
            m = fma2(splat2(cdt), accQ, m);      // M += cdt * (v.Vw)
            Mst[rc * 32 + rg] = m;
            const float2 pv = unpk2(accP);
            const float2 mv = unpk2(m);
            const float sg = sing_s[rc];
            qs[(r2 + 0) * TB + rc] = pv.x * pv.x * (1.0f + PLASTICITY * tanh_fast(mv.x)) * sg;
            qs[(r2 + 1) * TB + rc] = pv.y * pv.y * (1.0f + PLASTICITY * tanh_fast(mv.y)) * sg;
        }
        __syncthreads();

        // ---- phase 3: gamma = q.W, two-buffer W rotation (no copies, dist-2);
        //      v += ddt*(force - gamma) ----
        {
            ull Acc[16];
            #pragma unroll
            for (int c = 0; c < 16; ++c) Acc[c] = 0ull;

            float4 wa0 = *(const float4*)(Wm + k4);
            float4 wa1 = *(const float4*)(Wm + Dd + k4);
            float4 wb0 = *(const float4*)(Wm + 2 * (size_t)Dd + k4);
            float4 wb1 = *(const float4*)(Wm + 3 * (size_t)Dd + k4);

            #pragma unroll 1
            for (int r = 0; r < 56; r += 4) {
                gw2(qs, r, wa0, wa1, Acc);
                wa0 = *(const float4*)(Wm + (size_t)(r + 4) * Dd + k4);
                wa1 = *(const float4*)(Wm + (size_t)(r + 5) * Dd + k4);
                gw2(qs, r + 2, wb0, wb1, Acc);
                wb0 = *(const float4*)(Wm + (size_t)(r + 6) * Dd + k4);
                wb1 = *(const float4*)(Wm + (size_t)(r + 7) * Dd + k4);
            }
            gw2(qs, 56, wa0, wa1, Acc);
            wa0 = *(const float4*)(Wm + (size_t)60 * Dd + k4);
            wa1 = *(const float4*)(Wm + (size_t)61 * Dd + k4);
            gw2(qs, 58, wb0, wb1, Acc);
            wb0 = *(const float4*)(Wm + (size_t)62 * Dd + k4);
            wb1 = *(const float4*)(Wm + (size_t)63 * Dd + k4);
            gw2(qs, 60, wa0, wa1, Acc);
            gw2(qs, 62, wb0, wb1, Acc);

            #pragma unroll
            for (int p = 0; p < 4; ++p) {
                const float2 g0 = unpk2(Acc[0 * 4 + p]);
                const float2 g1 = unpk2(Acc[1 * 4 + p]);
                const float2 g2 = unpk2(Acc[2 * 4 + p]);
                const float2 g3 = unpk2(Acc[3 * 4 + p]);
                const int re = 2 * p;
                {
                    const float4 f = fpre[re];
                    float4* vp = (float4*)(vs + re * Dd + k4);
                    float4 vv = *vp;
                    vv.x += ddt * (f.x - g0.x);
                    vv.y += ddt * (f.y - g1.x);
                    vv.z += ddt * (f.z - g2.x);
                    vv.w += ddt * (f.w - g3.x);
                    *vp = vv;
                }
                {
                    const int ro = re + 1;
                    const float4 f = fpre[ro];
                    float4* vp = (float4*)(vs + ro * Dd + k4);
                    float4 vv = *vp;
                    vv.x += ddt * (f.x - g0.y);
                    vv.y += ddt * (f.y - g1.y);
                    vv.z += ddt * (f.z - g2.y);
                    vv.w += ddt * (f.w - g3.y);
                    *vp = vv;
                }
            }
        }
    }

    // ---- store: out.x = xs + C4*dt*vs (final drift fused), out.v = vs ----
    __syncthreads();
    {
        const float fc = (nkicks > 0) ? C4DT : 0.0f;
        float4* ox = (float4*)(out + (size_t)row0 * Dd);
        float4* ov = (float4*)(out + (size_t)Bsz * Dd + (size_t)row0 * Dd);
        #pragma unroll
        for (int i = tid; i < TB * Dd / 4; i += NT) {
            const float4 xv = sx4[i];
            const float4 vv = sv4[i];
            float4 o;
            o.x = xv.x + fc * vv.x; o.y = xv.y + fc * vv.y;
            o.z = xv.z + fc * vv.z; o.w = xv.w + fc * vv.w;
            ox[i] = o;
            ov[i] = vv;
        }
    }
}

extern "C" void kernel_launch(void* const* d_in, const int* in_sizes, int n_in,
                              void* d_out, int out_size) {
    const float* x     = (const float*)d_in[0];
    const float* v     = (const float*)d_in[1];
    const float* force = (const float*)d_in[2];
    const float* U     = (const float*)d_in[3];
    const float* W     = (const float*)d_in[4];
    const float* Vw    = (const float*)d_in[5];
    const int*   steps = (const int*)d_in[6];

    const size_t smem = (size_t)(2 * TB * Dd + Rr * TB + TB) * sizeof(float)
                      + (size_t)(16 * 256 + 256) * sizeof(ull);
    cudaFuncSetAttribute(yoshida_kernel,
                         cudaFuncAttributeMaxDynamicSharedMemorySize, (int)smem);
    yoshida_kernel<<<Bsz / TB, NT, smem>>>(x, v, force, U, W, Vw, steps, (float*)d_out);
}

// round 14
// speedup vs baseline: 1.0374x; 1.0374x over previous
#include <cuda_runtime.h>
#include <math.h>

#define Bsz 8192
#define Dd  1024
#define Rr  64
#define TB  8
#define NT  256

typedef unsigned long long ull;

// ---- Yoshida 4th-order coefficients ----
constexpr double kCbrt2 = 1.2599210498948731647672106072782;
constexpr double kW1 = 1.0 / (2.0 - kCbrt2);
constexpr double kW0 = -kCbrt2 * kW1;
constexpr double kDT = 0.01;

#define C1DT  ((float)((kW1 * 0.5) * kDT))
#define C2DT  ((float)(((kW0 + kW1) * 0.5) * kDT))
#define C4DT  C1DT
#define C41DT ((float)(kW1 * kDT))          // (C4 + C1) * dt
#define D1DT  ((float)(kW1 * kDT))
#define D2DT  ((float)(kW0 * kDT))

#define PLASTICITY    0.1f
#define SING_THRESH   10.0f
#define SING_STRENGTH 20.0f

// ---- packed f32x2 helpers (Blackwell) ----
__device__ __forceinline__ ull splat2(float x) {
    ull r; asm("mov.b64 %0, {%1, %1};" : "=l"(r) : "f"(x)); return r;
}
__device__ __forceinline__ ull fma2(ull a, ull b, ull c) {
    ull d; asm("fma.rn.f32x2 %0, %1, %2, %3;" : "=l"(d) : "l"(a), "l"(b), "l"(c)); return d;
}
__device__ __forceinline__ ull add2(ull a, ull b) {
    ull d; asm("add.rn.f32x2 %0, %1, %2;" : "=l"(d) : "l"(a), "l"(b)); return d;
}
__device__ __forceinline__ float2 unpk2(ull v) {
    float2 r; asm("mov.b64 {%0, %1}, %2;" : "=f"(r.x), "=f"(r.y) : "l"(v)); return r;
}
__device__ __forceinline__ float tanh_fast(float x) {
    float r; asm("tanh.approx.f32 %0, %1;" : "=f"(r) : "f"(x)); return r;
}

// Fused PQ block: 4 d's, 8 rows, one r-pair per matrix.
// A[0..7] = P rows (v.U), A[8..15] = Q rows (v.Vw). Shared splats.
__device__ __forceinline__ void pq_block(const float* __restrict__ sb, int d,
                                         const ull* u, const ull* w, ull* A)
{
    #pragma unroll
    for (int half = 0; half < 2; ++half) {
        float4 sv[4];
        #pragma unroll
        for (int j = 0; j < 4; ++j)
            sv[j] = *(const float4*)(sb + (half * 4 + j) * Dd + d);
        #pragma unroll
        for (int dd = 0; dd < 4; ++dd) {
            #pragma unroll
            for (int j = 0; j < 4; ++j) {
                const float f = (dd == 0) ? sv[j].x : (dd == 1) ? sv[j].y
                              : (dd == 2) ? sv[j].z : sv[j].w;
                const ull sp = splat2(f);
                const int row = half * 4 + j;
                A[row]     = fma2(sp, u[dd], A[row]);
                A[8 + row] = fma2(sp, w[dd], A[8 + row]);
            }
        }
    }
}

#define PQ_LOAD(ub, wb, dbase)                                              \
    do {                                                                    \
        _Pragma("unroll")                                                   \
        for (int dd = 0; dd < 4; ++dd) {                                    \
            ub[dd] = *(const ull*)(mu + (size_t)((dbase) + dd) * Rr);       \
            wb[dd] = *(const ull*)(mv + (size_t)((dbase) + dd) * Rr);       \
        }                                                                   \
    } while (0)

// Fused pass: P = v.U and Q = v.Vw over a 128-d slice, 8 rows, r-pair r2.
// Three-buffer rotation: no register copies, prefetch distance = 3 blocks.
__device__ __forceinline__ void pq_pass(const float* __restrict__ st,
                                        const float* __restrict__ U,
                                        const float* __restrict__ Vw,
                                        int r2, int d0, ull* A)
{
    #pragma unroll
    for (int c = 0; c < 16; ++c) A[c] = 0ull;
    const float* sb = st + d0;
    const float* mu = U  + (size_t)d0 * Rr + r2;
    const float* mv = Vw + (size_t)d0 * Rr + r2;

    ull u0[4], w0[4], u1[4], w1[4], u2[4], w2[4];
    PQ_LOAD(u0, w0, 0);
    PQ_LOAD(u1, w1, 4);
    PQ_LOAD(u2, w2, 8);

    #pragma unroll 1
    for (int d = 0; d < 96; d += 12) {
        pq_block(sb, d,     u0, w0, A); PQ_LOAD(u0, w0, d + 12);
        pq_block(sb, d + 4, u1, w1, A); PQ_LOAD(u1, w1, d + 16);
        pq_block(sb, d + 8, u2, w2, A); PQ_LOAD(u2, w2, d + 20);
    }
    pq_block(sb,  96, u0, w0, A); PQ_LOAD(u0, w0, 108);
    pq_block(sb, 100, u1, w1, A); PQ_LOAD(u1, w1, 112);
    pq_block(sb, 104, u2, w2, A); PQ_LOAD(u2, w2, 116);
    pq_block(sb, 108, u0, w0, A); PQ_LOAD(u0, w0, 120);
    pq_block(sb, 112, u1, w1, A); PQ_LOAD(u1, w1, 124);
    pq_block(sb, 116, u2, w2, A);
    pq_block(sb, 120, u0, w0, A);
    pq_block(sb, 124, u1, w1, A);
}

// Init pass: B[0..7] = x.Vw rows over a 128-d slice.
__device__ __forceinline__ void m_init_pass(const float* __restrict__ st,
                                            const float* __restrict__ Vw,
                                            int r2, int d0, ull* B)
{
    #pragma unroll
    for (int c = 0; c < 8; ++c) B[c] = 0ull;
    const float* sb = st + d0;
    const float* mv = Vw + (size_t)d0 * Rr + r2;
    #pragma unroll 1
    for (int d = 0; d < 128; d += 4) {
        ull w[4];
        #pragma unroll
        for (int dd = 0; dd < 4; ++dd)
            w[dd] = *(const ull*)(mv + (size_t)(d + dd) * Rr);
        #pragma unroll
        for (int half = 0; half < 2; ++half) {
            float4 sv[4];
            #pragma unroll
            for (int j = 0; j < 4; ++j)
                sv[j] = *(const float4*)(sb + (half * 4 + j) * Dd + d);
            #pragma unroll
            for (int dd = 0; dd < 4; ++dd) {
                #pragma unroll
                for (int j = 0; j < 4; ++j) {
                    const float f = (dd == 0) ? sv[j].x : (dd == 1) ? sv[j].y
                                  : (dd == 2) ? sv[j].z : sv[j].w;
                    B[half * 4 + j] = fma2(splat2(f), w[dd], B[half * 4 + j]);
                }
            }
        }
    }
}

// Balanced-tree reduce of 8 SMEM partials (stride 32 ull) at base+rg.
__device__ __forceinline__ ull tree8(const ull* __restrict__ base, int rg)
{
    ull t[8];
    #pragma unroll
    for (int p = 0; p < 8; ++p)
        t[p] = base[p * 32 + rg];
    #pragma unroll
    for (int p = 0; p < 4; ++p) t[p] = add2(t[p], t[p + 4]);
    t[0] = add2(t[0], t[2]);
    t[1] = add2(t[1], t[3]);
    return add2(t[0], t[1]);
}

// Phase-3 2-row block: Acc[k*4 + rowpair] += q(rows, r..r+1) * W splats.
__device__ __forceinline__ void gw2(const float* __restrict__ qs, int r,
                                    const float4 wA, const float4 wB, ull* Acc)
{
    const ulonglong2 qa0 = *(const ulonglong2*)(qs + r * TB);
    const ulonglong2 qb0 = *(const ulonglong2*)(qs + r * TB + 4);
    const ulonglong2 qa1 = *(const ulonglong2*)(qs + (r + 1) * TB);
    const ulonglong2 qb1 = *(const ulonglong2*)(qs + (r + 1) * TB + 4);
    {
        const ull s0 = splat2(wA.x), s1 = splat2(wA.y);
        const ull s2 = splat2(wA.z), s3 = splat2(wA.w);
        Acc[0]  = fma2(qa0.x, s0, Acc[0]);  Acc[1]  = fma2(qa0.y, s0, Acc[1]);
        Acc[2]  = fma2(qb0.x, s0, Acc[2]);  Acc[3]  = fma2(qb0.y, s0, Acc[3]);
        Acc[4]  = fma2(qa0.x, s1, Acc[4]);  Acc[5]  = fma2(qa0.y, s1, Acc[5]);
        Acc[6]  = fma2(qb0.x, s1, Acc[6]);  Acc[7]  = fma2(qb0.y, s1, Acc[7]);
        Acc[8]  = fma2(qa0.x, s2, Acc[8]);  Acc[9]  = fma2(qa0.y, s2, Acc[9]);
        Acc[10] = fma2(qb0.x, s2, Acc[10]); Acc[11] = fma2(qb0.y, s2, Acc[11]);
        Acc[12] = fma2(qa0.x, s3, Acc[12]); Acc[13] = fma2(qa0.y, s3, Acc[13]);
        Acc[14] = fma2(qb0.x, s3, Acc[14]); Acc[15] = fma2(qb0.y, s3, Acc[15]);
    }
    {
        const ull s0 = splat2(wB.x), s1 = splat2(wB.y);
        const ull s2 = splat2(wB.z), s3 = splat2(wB.w);
        Acc[0]  = fma2(qa1.x, s0, Acc[0]);  Acc[1]  = fma2(qa1.y, s0, Acc[1]);
        Acc[2]  = fma2(qb1.x, s0, Acc[2]);  Acc[3]  = fma2(qb1.y, s0, Acc[3]);
        Acc[4]  = fma2(qa1.x, s1, Acc[4]);  Acc[5]  = fma2(qa1.y, s1, Acc[5]);
        Acc[6]  = fma2(qb1.x, s1, Acc[6]);  Acc[7]  = fma2(qb1.y, s1, Acc[7]);
        Acc[8]  = fma2(qa1.x, s2, Acc[8]);  Acc[9]  = fma2(qa1.y, s2, Acc[9]);
        Acc[10] = fma2(qb1.x, s2, Acc[10]); Acc[11] = fma2(qb1.y, s2, Acc[11]);
        Acc[12] = fma2(qa1.x, s3, Acc[12]); Acc[13] = fma2(qa1.y, s3, Acc[13]);
        Acc[14] = fma2(qb1.x, s3, Acc[14]); Acc[15] = fma2(qb1.y, s3, Acc[15]);
    }
}

#define W_LOAD(b0, b1, rr)                                                   \
    do {                                                                     \
        b0 = *(const float4*)(Wm + (size_t)(rr) * Dd + k4);                  \
        b1 = *(const float4*)(Wm + (size_t)((rr) + 1) * Dd + k4);            \
    } while (0)

__global__ void __launch_bounds__(NT, 2)
yoshida_kernel(const float* __restrict__ x_in,
               const float* __restrict__ v_in,
               const float* __restrict__ force,
               const float* __restrict__ U,     // [D, R]
               const float* __restrict__ Wm,    // [R, D]
               const float* __restrict__ Vw,    // [D, R]
               const int*   __restrict__ steps_p,
               float* __restrict__ out)         // [x(B*D) ; v(B*D)]
{
    extern __shared__ float smem[];
    float* xs     = smem;                       // 8192 floats
    float* vs     = xs + TB * Dd;               // 8192
    float* qs     = vs + TB * Dd;               // 512  (qs[r*TB + row], sing folded)
    float* sing_s = qs + Rr * TB;               // 8
    ull*   part   = (ull*)(sing_s + TB);        // 16*256 ull = 32KB
    ull*   Mst    = part + 16 * 256;            // 256 ull = 2KB  (M state)

    const int tid  = threadIdx.x;
    const int row0 = blockIdx.x * TB;

    float4* sx4 = (float4*)xs;
    float4* sv4 = (float4*)vs;

    // ---- fused-pass mapping: 32 r-pairs x 8 d-slices ----
    const int rg = tid & 31;                    // r-pair 0..31
    const int r2 = rg * 2;
    const int ds = tid >> 5;                    // 0..7
    const int d0 = ds * 128;
    // ---- reduce mapping: 8 rows x 32 r-pairs ----
    const int rc = tid >> 5;                    // row 0..7
    // ---- phase-3 mapping: 256 k-quads, all 8 rows ----
    const int k4 = tid * 4;
    // ---- drift mapping: warp per row ----
    const int drow = tid >> 5;
    const int lane = tid & 31;

    // ---- load state tile ----
    {
        const float4* gx = (const float4*)(x_in + (size_t)row0 * Dd);
        const float4* gv = (const float4*)(v_in + (size_t)row0 * Dd);
        #pragma unroll
        for (int i = tid; i < TB * Dd / 4; i += NT) {
            sx4[i] = gx[i];
            sv4[i] = gv[i];
        }
    }
    __syncthreads();

    // ---- init M state: M = x0 . Vw ----
    {
        ull B[8];
        m_init_pass(xs, Vw, r2, d0, B);
        #pragma unroll
        for (int c = 0; c < 8; ++c)
            part[c * 256 + ds * 32 + rg] = B[c];
        __syncthreads();
        Mst[rc * 32 + rg] = tree8(part + rc * 256, rg);
    }

    const int nkicks = 3 * (*steps_p);

    for (int k = 0; k < nkicks; ++k) {
        const int sub = k - (k / 3) * 3;
        const float cdt = (k == 0) ? C1DT : (sub == 0) ? C41DT : C2DT;
        const float ddt = (sub == 1) ? D2DT : D1DT;

        __syncthreads();   // vs from prev kick visible; part readers done

        ull A[16];

        // ---- fused PQ-pass: P = v.U, Q = v.Vw (pre-kick v) ----
        pq_pass(vs, U, Vw, r2, d0, A);
        #pragma unroll
        for (int c = 0; c < 16; ++c)
            part[c * 256 + ds * 32 + rg] = A[c];

        // ---- drift + sing fused (warp per row, packed FMA2) ----
        {
            ulonglong2* xr = (ulonglong2*)(xs + drow * Dd);
            const ulonglong2* vr = (const ulonglong2*)(vs + drow * Dd);
            const ull cd2 = splat2(cdt);
            ull acc2 = 0ull;
            #pragma unroll
            for (int i = 0; i < 8; ++i) {
                ulonglong2 xv = xr[lane + 32 * i];
                const ulonglong2 vv = vr[lane + 32 * i];
                xv.x = fma2(cd2, vv.x, xv.x);
                xv.y = fma2(cd2, vv.y, xv.y);
                acc2 = fma2(xv.x, xv.x, acc2);
                acc2 = fma2(xv.y, xv.y, acc2);
                xr[lane + 32 * i] = xv;
            }
            const float2 a2 = unpk2(acc2);
            float acc = a2.x + a2.y;
            #pragma unroll
            for (int o = 16; o; o >>= 1)
                acc += __shfl_xor_sync(0xffffffffu, acc, o);
            if (lane == 0)
                sing_s[drow] = 1.0f + SING_STRENGTH * __expf(-acc * (1.0f / SING_THRESH));
        }
        __syncthreads();   // partials + sing ready

        // ---- combined reduce: P, Q -> M update -> q epilogue ----
        {
            const ull accP = tree8(part + rc * 256, rg);
            const ull accQ = tree8(part + (8 + rc) * 256, rg);
            ull m = Mst[rc * 32 + rg];
            m = fma2(splat2(cdt), accQ, m);      // M += cdt * (v.Vw)
            Mst[rc * 32 + rg] = m;
            const float2 pv = unpk2(accP);
            const float2 mv = unpk2(m);
            const float sg = sing_s[rc];
            qs[(r2 + 0) * TB + rc] = pv.x * pv.x * (1.0f + PLASTICITY * tanh_fast(mv.x)) * sg;
            qs[(r2 + 1) * TB + rc] = pv.y * pv.y * (1.0f + PLASTICITY * tanh_fast(mv.y)) * sg;
        }
        __syncthreads();

        // ---- phase 3: gamma = q.W, three-pair W rotation (dist-6 rows);
        //      v += ddt*(force - gamma) ----
        {
            ull Acc[16];
            #pragma unroll
            for (int c = 0; c < 16; ++c) Acc[c] = 0ull;

            float4 wa0, wa1, wb0, wb1, wc0, wc1;
            W_LOAD(wa0, wa1, 0);
            W_LOAD(wb0, wb1, 2);
            W_LOAD(wc0, wc1, 4);

            #pragma unroll 1
            for (int r = 0; r < 48; r += 6) {
                gw2(qs, r,     wa0, wa1, Acc); W_LOAD(wa0, wa1, r + 6);
                gw2(qs, r + 2, wb0, wb1, Acc); W_LOAD(wb0, wb1, r + 8);
                gw2(qs, r + 4, wc0, wc1, Acc); W_LOAD(wc0, wc1, r + 10);
            }

            // force loads here: ~8 gw2 blocks (~400 wall cyc) before use
            float4 fpre[8];
            #pragma unroll
            for (int j = 0; j < 8; ++j)
                fpre[j] = *(const float4*)(force + (size_t)(row0 + j) * Dd + k4);

            gw2(qs, 48, wa0, wa1, Acc); W_LOAD(wa0, wa1, 54);
            gw2(qs, 50, wb0, wb1, Acc); W_LOAD(wb0, wb1, 56);
            gw2(qs, 52, wc0, wc1, Acc); W_LOAD(wc0, wc1, 58);
            gw2(qs, 54, wa0, wa1, Acc); W_LOAD(wa0, wa1, 60);
            gw2(qs, 56, wb0, wb1, Acc); W_LOAD(wb0, wb1, 62);
            gw2(qs, 58, wc0, wc1, Acc);
            gw2(qs, 60, wa0, wa1, Acc);
            gw2(qs, 62, wb0, wb1, Acc);

            #pragma unroll
            for (int p = 0; p < 4; ++p) {
                const float2 g0 = unpk2(Acc[0 * 4 + p]);
                const float2 g1 = unpk2(Acc[1 * 4 + p]);
                const float2 g2 = unpk2(Acc[2 * 4 + p]);
                const float2 g3 = unpk2(Acc[3 * 4 + p]);
                const int re = 2 * p;
                {
                    const float4 f = fpre[re];
                    float4* vp = (float4*)(vs + re * Dd + k4);
                    float4 vv = *vp;
                    vv.x += ddt * (f.x - g0.x);
                    vv.y += ddt * (f.y - g1.x);
                    vv.z += ddt * (f.z - g2.x);
                    vv.w += ddt * (f.w - g3.x);
                    *vp = vv;
                }
                {
                    const int ro = re + 1;
                    const float4 f = fpre[ro];
                    float4* vp = (float4*)(vs + ro * Dd + k4);
                    float4 vv = *vp;
                    vv.x += ddt * (f.x - g0.y);
                    vv.y += ddt * (f.y - g1.y);
                    vv.z += ddt * (f.z - g2.y);
                    vv.w += ddt * (f.w - g3.y);
                    *vp = vv;
                }
            }
        }
    }

    // ---- store: out.x = xs + C4*dt*vs (final drift fused), out.v = vs ----
    __syncthreads();
    {
        const float fc = (nkicks > 0) ? C4DT : 0.0f;
        float4* ox = (float4*)(out + (size_t)row0 * Dd);
        float4* ov = (float4*)(out + (size_t)Bsz * Dd + (size_t)row0 * Dd);
        #pragma unroll
        for (int i = tid; i < TB * Dd / 4; i += NT) {
            const float4 xv = sx4[i];
            const float4 vv = sv4[i];
            float4 o;
            o.x = xv.x + fc * vv.x; o.y = xv.y + fc * vv.y;
            o.z = xv.z + fc * vv.z; o.w = xv.w + fc * vv.w;
            ox[i] = o;
            ov[i] = vv;
        }
    }
}

extern "C" void kernel_launch(void* const* d_in, const int* in_sizes, int n_in,
                              void* d_out, int out_size) {
    const float* x     = (const float*)d_in[0];
    const float* v     = (const float*)d_in[1];
    const float* force = (const float*)d_in[2];
    const float* U     = (const float*)d_in[3];
    const float* W     = (const float*)d_in[4];
    const float* Vw    = (const float*)d_in[5];
    const int*   steps = (const int*)d_in[6];

    const size_t smem = (size_t)(2 * TB * Dd + Rr * TB + TB) * sizeof(float)
                      + (size_t)(16 * 256 + 256) * sizeof(ull);
    cudaFuncSetAttribute(yoshida_kernel,
                         cudaFuncAttributeMaxDynamicSharedMemorySize, (int)smem);
    yoshida_kernel<<<Bsz / TB, NT, smem>>>(x, v, force, U, W, Vw, steps, (float*)d_out);
}